// round 12
// baseline (speedup 1.0000x reference)
#include <cuda_runtime.h>
#include <cuda_bf16.h>
#include <cstdint>

#define B_  8
#define L_  1024
#define D_  768
#define H_  12
#define DH_ 64

// ---------------- scratch (__device__ globals; no allocation allowed) ------
__device__ __nv_bfloat16 g_xhi [B_ * L_ * D_];   // split of x
__device__ __nv_bfloat16 g_xlo [B_ * L_ * D_];
__device__ __nv_bfloat16 g_khi [B_ * L_ * D_];   // split of K projection
__device__ __nv_bfloat16 g_klo [B_ * L_ * D_];
__device__ __nv_bfloat16 g_vhi [B_ * L_ * D_];   // split of attention output
__device__ __nv_bfloat16 g_vlo [B_ * L_ * D_];
__device__ __nv_bfloat16 g_wkhi[D_ * D_];
__device__ __nv_bfloat16 g_wklo[D_ * D_];
__device__ __nv_bfloat16 g_wohi[D_ * D_];
__device__ __nv_bfloat16 g_wolo[D_ * D_];

// ---------------------------------------------------------------------------
// helpers
// ---------------------------------------------------------------------------
__device__ __forceinline__ uint32_t smem_u32(const void* p) {
    uint32_t a;
    asm("{ .reg .u64 t; cvta.to.shared.u64 t, %1; cvt.u32.u64 %0, t; }"
        : "=r"(a) : "l"(p));
    return a;
}
__device__ __forceinline__ void ldsm_x4(uint32_t* r, uint32_t addr) {
    asm volatile("ldmatrix.sync.aligned.m8n8.x4.shared.b16 {%0,%1,%2,%3}, [%4];"
                 : "=r"(r[0]), "=r"(r[1]), "=r"(r[2]), "=r"(r[3]) : "r"(addr));
}
__device__ __forceinline__ void ldsm_x2(uint32_t* r, uint32_t addr) {
    asm volatile("ldmatrix.sync.aligned.m8n8.x2.shared.b16 {%0,%1}, [%2];"
                 : "=r"(r[0]), "=r"(r[1]) : "r"(addr));
}
__device__ __forceinline__ void ldsm_x4t(uint32_t* r, uint32_t addr) {
    asm volatile("ldmatrix.sync.aligned.m8n8.x4.trans.shared.b16 {%0,%1,%2,%3}, [%4];"
                 : "=r"(r[0]), "=r"(r[1]), "=r"(r[2]), "=r"(r[3]) : "r"(addr));
}
__device__ __forceinline__ void mma_bf16(float* c, const uint32_t* a,
                                         const uint32_t* b) {
    asm volatile(
        "mma.sync.aligned.m16n8k16.row.col.f32.bf16.bf16.f32 "
        "{%0,%1,%2,%3}, {%4,%5,%6,%7}, {%8,%9}, {%0,%1,%2,%3};"
        : "+f"(c[0]), "+f"(c[1]), "+f"(c[2]), "+f"(c[3])
        : "r"(a[0]), "r"(a[1]), "r"(a[2]), "r"(a[3]), "r"(b[0]), "r"(b[1]));
}
__device__ __forceinline__ float ex2f(float x) {
    float r;
    asm("ex2.approx.f32 %0, %1;" : "=f"(r) : "f"(x));
    return r;
}
__device__ __forceinline__ uint32_t packbf(float l, float h) {
    uint32_t r;
    asm("cvt.rn.bf16x2.f32 %0, %1, %2;" : "=r"(r) : "f"(h), "f"(l));
    return r;
}
__device__ __forceinline__ float lowf(uint32_t u) { return __uint_as_float(u << 16); }
__device__ __forceinline__ float hif(uint32_t u)  { return __uint_as_float(u & 0xFFFF0000u); }

#define CP_ASYNC16(saddr, gaddr) \
    asm volatile("cp.async.ca.shared.global [%0], [%1], 16;" \
                 :: "r"(saddr), "l"(gaddr) : "memory")
#define CP_COMMIT() asm volatile("cp.async.commit_group;" ::: "memory")
#define CP_WAIT(n)  asm volatile("cp.async.wait_group %0;" :: "n"(n) : "memory")

// ---------------------------------------------------------------------------
// split: fp32 -> (hi bf16, lo bf16)
// ---------------------------------------------------------------------------
__global__ void split_fp32(const float* __restrict__ in,
                           __nv_bfloat16* __restrict__ hi,
                           __nv_bfloat16* __restrict__ lo, int n4) {
    int i = blockIdx.x * blockDim.x + threadIdx.x;
    if (i >= n4) return;
    float4 v = ((const float4*)in)[i];
    uint32_t h0 = packbf(v.x, v.y), h1 = packbf(v.z, v.w);
    uint32_t l0 = packbf(v.x - lowf(h0), v.y - hif(h0));
    uint32_t l1 = packbf(v.z - lowf(h1), v.w - hif(h1));
    ((uint2*)hi)[i] = make_uint2(h0, h1);
    ((uint2*)lo)[i] = make_uint2(l0, l1);
}

// ---------------------------------------------------------------------------
// split-bf16 tensor-core GEMM: C[M,768] = A[M,768] * W[768,768]^T + bias
// CTA 128Mx64N, K-block 32, 8 warps (2Mx4N -> warp 64x16), double-buffered.
// 3 CTAs/SM target (smem 60KB, regs capped by launch_bounds).
// ---------------------------------------------------------------------------
#define GKD    768
#define GROWB  80
#define GOFF_AHI 0
#define GOFF_ALO 10240
#define GOFF_BHI 20480
#define GOFF_BLO 25600
#define GBUF   30720
#define GSMEM_TOTAL (2 * GBUF)

__global__ __launch_bounds__(256, 3)
void gemm_mma_split(const __nv_bfloat16* __restrict__ Ahi,
                    const __nv_bfloat16* __restrict__ Alo,
                    const __nv_bfloat16* __restrict__ Bhi,
                    const __nv_bfloat16* __restrict__ Blo,
                    const float* __restrict__ bias,
                    float* __restrict__ Cf,
                    __nv_bfloat16* __restrict__ Chi,
                    __nv_bfloat16* __restrict__ Clo) {
    extern __shared__ char smc[];
    const uint32_t sb = smem_u32(smc);
    const int tid  = threadIdx.x;
    const int lane = tid & 31;
    const int wid  = tid >> 5;
    const int wm   = wid & 1;
    const int wn   = wid >> 1;
    const int m0 = blockIdx.y * 128;
    const int n0 = blockIdx.x * 64;

    const char* gAhi = (const char*)(Ahi + (size_t)m0 * GKD);
    const char* gAlo = (const char*)(Alo + (size_t)m0 * GKD);
    const char* gBhi = (const char*)(Bhi + (size_t)n0 * GKD);
    const char* gBlo = (const char*)(Blo + (size_t)n0 * GKD);

    // A loaders: 512 chunks/matrix, 2/thread.  B: 256 chunks/matrix, 1/thread.
    const int ar0 = (tid * 2) >> 2,     ac0 = (tid * 2) & 3;
    const int ar1 = (tid * 2 + 1) >> 2, ac1 = (tid * 2 + 1) & 3;
    const int br  = tid >> 2,           bc  = tid & 3;

#define GISSUE(kb, buf) do {                                                   \
    const uint32_t bb = sb + (buf) * GBUF;                                     \
    const size_t g0 = (size_t)ar0 * (GKD * 2) + (kb) * 64 + ac0 * 16;          \
    const size_t g1 = (size_t)ar1 * (GKD * 2) + (kb) * 64 + ac1 * 16;          \
    const size_t g2 = (size_t)br  * (GKD * 2) + (kb) * 64 + bc  * 16;          \
    CP_ASYNC16(bb + GOFF_AHI + ar0 * GROWB + ac0 * 16, gAhi + g0);             \
    CP_ASYNC16(bb + GOFF_AHI + ar1 * GROWB + ac1 * 16, gAhi + g1);             \
    CP_ASYNC16(bb + GOFF_ALO + ar0 * GROWB + ac0 * 16, gAlo + g0);             \
    CP_ASYNC16(bb + GOFF_ALO + ar1 * GROWB + ac1 * 16, gAlo + g1);             \
    CP_ASYNC16(bb + GOFF_BHI + br * GROWB + bc * 16,  gBhi + g2);              \
    CP_ASYNC16(bb + GOFF_BLO + br * GROWB + bc * 16,  gBlo + g2);              \
    CP_COMMIT();                                                               \
} while (0)

    float acc[4][2][4];
#pragma unroll
    for (int mt = 0; mt < 4; mt++)
#pragma unroll
        for (int nt = 0; nt < 2; nt++)
#pragma unroll
            for (int k = 0; k < 4; k++) acc[mt][nt][k] = 0.f;

    const uint32_t a_row  = wm * 64 + (lane & 15);
    const uint32_t a_koff = (lane >> 4) << 4;
    const uint32_t b_row  = wn * 16 + (lane & 7);
    const uint32_t b_koff = ((lane >> 3) & 1) << 4;

    GISSUE(0, 0);

    for (int kb = 0; kb < GKD / 32; kb++) {
        const int buf = kb & 1;
        if (kb + 1 < GKD / 32) {
            GISSUE(kb + 1, buf ^ 1);
            CP_WAIT(1);
        } else {
            CP_WAIT(0);
        }
        __syncthreads();

        const uint32_t bb = sb + buf * GBUF;
#pragma unroll
        for (int kk = 0; kk < 2; kk++) {
            const uint32_t ka = kk * 32 + a_koff;
            const uint32_t kbf = kk * 32 + b_koff;
            uint32_t bhi[2][2], blo[2][2];
#pragma unroll
            for (int nt = 0; nt < 2; nt++) {
                ldsm_x2(bhi[nt], bb + GOFF_BHI + (b_row + nt * 8) * GROWB + kbf);
                ldsm_x2(blo[nt], bb + GOFF_BLO + (b_row + nt * 8) * GROWB + kbf);
            }
#pragma unroll
            for (int mt = 0; mt < 4; mt++) {
                uint32_t ahi[4], alo[4];
                ldsm_x4(ahi, bb + GOFF_AHI + (a_row + mt * 16) * GROWB + ka);
                ldsm_x4(alo, bb + GOFF_ALO + (a_row + mt * 16) * GROWB + ka);
#pragma unroll
                for (int nt = 0; nt < 2; nt++) {
                    mma_bf16(acc[mt][nt], ahi, bhi[nt]);
                    mma_bf16(acc[mt][nt], ahi, blo[nt]);
                    mma_bf16(acc[mt][nt], alo, bhi[nt]);
                }
            }
        }
        __syncthreads();
    }

    // epilogue
#pragma unroll
    for (int nt = 0; nt < 2; nt++) {
        const int n = n0 + wn * 16 + nt * 8 + (lane & 3) * 2;
        const float b0 = bias[n], b1 = bias[n + 1];
#pragma unroll
        for (int mt = 0; mt < 4; mt++) {
            const int m = m0 + wm * 64 + mt * 16 + (lane >> 2);
            const float v00 = acc[mt][nt][0] + b0, v01 = acc[mt][nt][1] + b1;
            const float v10 = acc[mt][nt][2] + b0, v11 = acc[mt][nt][3] + b1;
            if (Cf) {
                *(float2*)&Cf[(size_t)m * GKD + n] = make_float2(v00, v01);
                *(float2*)&Cf[(size_t)(m + 8) * GKD + n] = make_float2(v10, v11);
            } else {
                uint32_t h0 = packbf(v00, v01);
                uint32_t l0 = packbf(v00 - lowf(h0), v01 - hif(h0));
                uint32_t h1 = packbf(v10, v11);
                uint32_t l1 = packbf(v10 - lowf(h1), v11 - hif(h1));
                *(uint32_t*)&Chi[(size_t)m * GKD + n] = h0;
                *(uint32_t*)&Clo[(size_t)m * GKD + n] = l0;
                *(uint32_t*)&Chi[(size_t)(m + 8) * GKD + n] = h1;
                *(uint32_t*)&Clo[(size_t)(m + 8) * GKD + n] = l1;
            }
        }
    }
#undef GISSUE
}

// ---------------------------------------------------------------------------
// mma.sync flash attention, split-bf16.  K-tile = 64 keys, 2 CTAs/SM target.
// Per (b,h): S = Kh Kh^T / sqrt(768) (row mask), softmax, O = P @ Kh.
// CTA: 128 q-rows, 8 warps x 16 rows; K double-buffered cp.async.
// ---------------------------------------------------------------------------
#define APITCH 144
#define ASQH   0
#define ASQL   18432
#define ASK    36864            // + buf*18432 ; lo at +9216
#define ASMEM_TOTAL (36864 + 2 * 18432)

__global__ __launch_bounds__(256, 2)
void attn_mma(const __nv_bfloat16* __restrict__ Khi,
              const __nv_bfloat16* __restrict__ Klo,
              const int* __restrict__ mask,
              __nv_bfloat16* __restrict__ Vhi,
              __nv_bfloat16* __restrict__ Vlo) {
    extern __shared__ char smc[];
    const uint32_t sb = smem_u32(smc);
    const int tid  = threadIdx.x;
    const int lane = tid & 31;
    const int w    = tid >> 5;
    const int q0 = blockIdx.x * 128;
    const int h  = blockIdx.y;
    const int b  = blockIdx.z;

    const size_t gk = ((size_t)b * L_) * D_ + h * DH_;
    const size_t gq = gk + (size_t)q0 * D_;

    // Q loader: 1024 chunks/matrix, 4/thread.  K tile: 512 chunks, 2/thread.
    const int qrow[4] = {(tid + 0) >> 3, (tid + 256) >> 3,
                         (tid + 512) >> 3, (tid + 768) >> 3};
    const int qcol[4] = {(tid + 0) & 7, (tid + 256) & 7,
                         (tid + 512) & 7, (tid + 768) & 7};
    const int kr0 = tid >> 3,           kc0 = tid & 7;
    const int kr1 = (tid + 256) >> 3,   kc1 = (tid + 256) & 7;

#define AISSUE_K(kt, buf) do {                                                 \
    const uint32_t dh = sb + ASK + (buf) * 18432;                              \
    const __nv_bfloat16* ghx = Khi + gk + (size_t)(kt) * 64 * D_;              \
    const __nv_bfloat16* glx = Klo + gk + (size_t)(kt) * 64 * D_;              \
    const uint32_t s0 = kr0 * APITCH + kc0 * 16;                               \
    const uint32_t s1 = kr1 * APITCH + kc1 * 16;                               \
    const size_t g0 = (size_t)kr0 * D_ + kc0 * 8;                              \
    const size_t g1 = (size_t)kr1 * D_ + kc1 * 8;                              \
    CP_ASYNC16(dh + s0, (const char*)(ghx + g0));                              \
    CP_ASYNC16(dh + s1, (const char*)(ghx + g1));                              \
    CP_ASYNC16(dh + 9216 + s0, (const char*)(glx + g0));                       \
    CP_ASYNC16(dh + 9216 + s1, (const char*)(glx + g1));                       \
    CP_COMMIT();                                                               \
} while (0)

    {
#pragma unroll
        for (int i = 0; i < 4; i++) {
            const uint32_t so = qrow[i] * APITCH + qcol[i] * 16;
            const size_t go = (size_t)qrow[i] * D_ + qcol[i] * 8;
            CP_ASYNC16(sb + ASQH + so, (const char*)(Khi + gq + go));
            CP_ASYNC16(sb + ASQL + so, (const char*)(Klo + gq + go));
        }
        CP_COMMIT();
    }
    AISSUE_K(0, 0);
    AISSUE_K(1, 1);

    CP_WAIT(2);
    __syncthreads();

    uint32_t qh[4][4], ql[4][4];
#pragma unroll
    for (int ks = 0; ks < 4; ks++) {
        const uint32_t a = sb + ASQH + (w * 16 + (lane & 15)) * APITCH +
                           ks * 32 + ((lane >> 4) << 4);
        ldsm_x4(qh[ks], a);
        ldsm_x4(ql[ks], a + 18432);
    }

    const bool rm0 = (__ldg(&mask[b * L_ + q0 + w * 16 + (lane >> 2)]) == 0);
    const bool rm1 = (__ldg(&mask[b * L_ + q0 + w * 16 + (lane >> 2) + 8]) == 0);
    const float kscale = 0.03608439182435161f * 1.4426950408889634f;

    float m0 = -3e38f, m1 = -3e38f, l0 = 0.f, l1 = 0.f;
    float o[8][4];
#pragma unroll
    for (int dn = 0; dn < 8; dn++)
#pragma unroll
        for (int j = 0; j < 4; j++) o[dn][j] = 0.f;

    for (int kt = 0; kt < L_ / 64; kt++) {
        if (kt < L_ / 64 - 1) { CP_WAIT(1); } else { CP_WAIT(0); }
        __syncthreads();
        const uint32_t kb = sb + ASK + (kt & 1) * 18432;

        // ---- S = Q K^T ----
        float s[8][4];
#pragma unroll
        for (int nb = 0; nb < 8; nb++)
#pragma unroll
            for (int j = 0; j < 4; j++) s[nb][j] = 0.f;

#pragma unroll
        for (int nb = 0; nb < 8; nb++) {
            uint32_t bh[8], bl[8];
            const uint32_t a0 = kb + (nb * 8 + (lane & 7)) * APITCH +
                                ((lane >> 3) << 4);
            ldsm_x4(bh, a0);
            ldsm_x4(bh + 4, a0 + 64);
            ldsm_x4(bl, a0 + 9216);
            ldsm_x4(bl + 4, a0 + 9216 + 64);
#pragma unroll
            for (int ks = 0; ks < 4; ks++) {
                mma_bf16(s[nb], qh[ks], bh + ks * 2);
                mma_bf16(s[nb], qh[ks], bl + ks * 2);
                mma_bf16(s[nb], ql[ks], bh + ks * 2);
            }
        }

        // ---- online softmax (exp2 domain) ----
        float tm0 = -3e38f, tm1 = -3e38f;
#pragma unroll
        for (int nb = 0; nb < 8; nb++) {
            s[nb][0] = rm0 ? -1e9f : s[nb][0] * kscale;
            s[nb][1] = rm0 ? -1e9f : s[nb][1] * kscale;
            s[nb][2] = rm1 ? -1e9f : s[nb][2] * kscale;
            s[nb][3] = rm1 ? -1e9f : s[nb][3] * kscale;
            tm0 = fmaxf(tm0, fmaxf(s[nb][0], s[nb][1]));
            tm1 = fmaxf(tm1, fmaxf(s[nb][2], s[nb][3]));
        }
        tm0 = fmaxf(tm0, __shfl_xor_sync(0xffffffffu, tm0, 1));
        tm0 = fmaxf(tm0, __shfl_xor_sync(0xffffffffu, tm0, 2));
        tm1 = fmaxf(tm1, __shfl_xor_sync(0xffffffffu, tm1, 1));
        tm1 = fmaxf(tm1, __shfl_xor_sync(0xffffffffu, tm1, 2));
        const float nm0 = fmaxf(m0, tm0), nm1 = fmaxf(m1, tm1);
        const float c0 = ex2f(m0 - nm0), c1 = ex2f(m1 - nm1);
        m0 = nm0; m1 = nm1;

        float ts0 = 0.f, ts1 = 0.f;
#pragma unroll
        for (int nb = 0; nb < 8; nb++) {
            s[nb][0] = ex2f(s[nb][0] - nm0);
            s[nb][1] = ex2f(s[nb][1] - nm0);
            s[nb][2] = ex2f(s[nb][2] - nm1);
            s[nb][3] = ex2f(s[nb][3] - nm1);
            ts0 += s[nb][0] + s[nb][1];
            ts1 += s[nb][2] + s[nb][3];
        }
        l0 = l0 * c0 + ts0;
        l1 = l1 * c1 + ts1;
#pragma unroll
        for (int dn = 0; dn < 8; dn++) {
            o[dn][0] *= c0; o[dn][1] *= c0;
            o[dn][2] *= c1; o[dn][3] *= c1;
        }

        // ---- O += P @ V (V = K tile) ----
#pragma unroll
        for (int kk = 0; kk < 4; kk++) {
            uint32_t ph[4], pl[4];
            {
                const float* sA = s[kk * 2];
                const float* sB = s[kk * 2 + 1];
                ph[0] = packbf(sA[0], sA[1]);
                ph[1] = packbf(sA[2], sA[3]);
                ph[2] = packbf(sB[0], sB[1]);
                ph[3] = packbf(sB[2], sB[3]);
                pl[0] = packbf(sA[0] - lowf(ph[0]), sA[1] - hif(ph[0]));
                pl[1] = packbf(sA[2] - lowf(ph[1]), sA[3] - hif(ph[1]));
                pl[2] = packbf(sB[0] - lowf(ph[2]), sB[1] - hif(ph[2]));
                pl[3] = packbf(sB[2] - lowf(ph[3]), sB[3] - hif(ph[3]));
            }
#pragma unroll
            for (int dn2 = 0; dn2 < 4; dn2++) {
                uint32_t vh[4], vl[4];
                const uint32_t a = kb + (kk * 16 + (lane & 15)) * APITCH +
                                   dn2 * 32 + ((lane >> 4) << 4);
                ldsm_x4t(vh, a);
                ldsm_x4t(vl, a + 9216);
                mma_bf16(o[dn2 * 2],     ph, vh);
                mma_bf16(o[dn2 * 2],     ph, vl);
                mma_bf16(o[dn2 * 2],     pl, vh);
                mma_bf16(o[dn2 * 2 + 1], ph, vh + 2);
                mma_bf16(o[dn2 * 2 + 1], ph, vl + 2);
                mma_bf16(o[dn2 * 2 + 1], pl, vh + 2);
            }
        }

        __syncthreads();
        if (kt + 2 < L_ / 64) AISSUE_K(kt + 2, kt & 1);
    }

    // ---- epilogue: normalize, split to bf16, store ----
    l0 += __shfl_xor_sync(0xffffffffu, l0, 1);
    l0 += __shfl_xor_sync(0xffffffffu, l0, 2);
    l1 += __shfl_xor_sync(0xffffffffu, l1, 1);
    l1 += __shfl_xor_sync(0xffffffffu, l1, 2);
    const float inv0 = 1.0f / l0, inv1 = 1.0f / l1;
    const int qa = q0 + w * 16 + (lane >> 2);
    const size_t ra = ((size_t)b * L_ + qa) * D_ + h * DH_;
    const size_t rb = ra + (size_t)8 * D_;
#pragma unroll
    for (int dn = 0; dn < 8; dn++) {
        const int col = dn * 8 + (lane & 3) * 2;
        const float v0 = o[dn][0] * inv0, v1 = o[dn][1] * inv0;
        const float v2 = o[dn][2] * inv1, v3 = o[dn][3] * inv1;
        uint32_t h0 = packbf(v0, v1);
        uint32_t l0p = packbf(v0 - lowf(h0), v1 - hif(h0));
        uint32_t h1 = packbf(v2, v3);
        uint32_t l1p = packbf(v2 - lowf(h1), v3 - hif(h1));
        *(uint32_t*)&Vhi[ra + col] = h0;
        *(uint32_t*)&Vlo[ra + col] = l0p;
        *(uint32_t*)&Vhi[rb + col] = h1;
        *(uint32_t*)&Vlo[rb + col] = l1p;
    }
#undef AISSUE_K
}

// ---------------------------------------------------------------------------
// Launch. Inputs: 0:x 1:mask 2:Wq 3:bq 4:Wk 5:bk 6:Wv 7:bv 8:Wo 9:bo
// (Q projection and Wv/bv are dead in the reference: V = K, scores = K K^T.)
// ---------------------------------------------------------------------------
extern "C" void kernel_launch(void* const* d_in, const int* in_sizes, int n_in,
                              void* d_out, int out_size) {
    const float* x    = (const float*)d_in[0];
    const int*   mask = (const int*)  d_in[1];
    const float* Wk   = (const float*)d_in[4];
    const float* bk   = (const float*)d_in[5];
    const float* Wo   = (const float*)d_in[8];
    const float* bo   = (const float*)d_in[9];
    float* out = (float*)d_out;

    __nv_bfloat16 *pxhi, *pxlo, *pkhi, *pklo, *pvhi, *pvlo;
    __nv_bfloat16 *pwkhi, *pwklo, *pwohi, *pwolo;
    cudaGetSymbolAddress((void**)&pxhi,  g_xhi);
    cudaGetSymbolAddress((void**)&pxlo,  g_xlo);
    cudaGetSymbolAddress((void**)&pkhi,  g_khi);
    cudaGetSymbolAddress((void**)&pklo,  g_klo);
    cudaGetSymbolAddress((void**)&pvhi,  g_vhi);
    cudaGetSymbolAddress((void**)&pvlo,  g_vlo);
    cudaGetSymbolAddress((void**)&pwkhi, g_wkhi);
    cudaGetSymbolAddress((void**)&pwklo, g_wklo);
    cudaGetSymbolAddress((void**)&pwohi, g_wohi);
    cudaGetSymbolAddress((void**)&pwolo, g_wolo);

    cudaFuncSetAttribute(gemm_mma_split,
                         cudaFuncAttributeMaxDynamicSharedMemorySize,
                         GSMEM_TOTAL);
    cudaFuncSetAttribute(attn_mma,
                         cudaFuncAttributeMaxDynamicSharedMemorySize,
                         ASMEM_TOTAL);

    const int M = B_ * L_;                    // 8192
    const int nx4 = M * D_ / 4;
    const int nw4 = D_ * D_ / 4;

    split_fp32<<<(nx4 + 255) / 256, 256>>>(x,  pxhi,  pxlo,  nx4);
    split_fp32<<<(nw4 + 255) / 256, 256>>>(Wk, pwkhi, pwklo, nw4);
    split_fp32<<<(nw4 + 255) / 256, 256>>>(Wo, pwohi, pwolo, nw4);

    // 1) K = x @ Wk^T + bk  -> split bf16
    {
        dim3 grid(D_ / 64, M / 128);
        gemm_mma_split<<<grid, 256, GSMEM_TOTAL>>>(pxhi, pxlo, pwkhi, pwklo,
                                                   bk, nullptr, pkhi, pklo);
    }
    // 2) fused flash attention on tensor cores -> split bf16 output
    {
        dim3 grid(L_ / 128, H_, B_);
        attn_mma<<<grid, 256, ASMEM_TOTAL>>>(pkhi, pklo, mask, pvhi, pvlo);
    }
    // 3) out = wV @ Wo^T + bo  -> fp32
    {
        dim3 grid(D_ / 64, M / 128);
        gemm_mma_split<<<grid, 256, GSMEM_TOTAL>>>(pvhi, pvlo, pwohi, pwolo,
                                                   bo, out, nullptr, nullptr);
    }
}

// round 13
// speedup vs baseline: 1.1120x; 1.1120x over previous
#include <cuda_runtime.h>
#include <cuda_bf16.h>
#include <cstdint>

#define B_  8
#define L_  1024
#define D_  768
#define H_  12
#define DH_ 64

// ---------------- scratch (__device__ globals; no allocation allowed) ------
__device__ __nv_bfloat16 g_xhi [B_ * L_ * D_];   // split of x
__device__ __nv_bfloat16 g_xlo [B_ * L_ * D_];
__device__ __nv_bfloat16 g_khi [B_ * L_ * D_];   // split of K projection
__device__ __nv_bfloat16 g_klo [B_ * L_ * D_];
__device__ __nv_bfloat16 g_vhi [B_ * L_ * D_];   // split of attention output
__device__ __nv_bfloat16 g_vlo [B_ * L_ * D_];
__device__ __nv_bfloat16 g_wkhi[D_ * D_];
__device__ __nv_bfloat16 g_wklo[D_ * D_];
__device__ __nv_bfloat16 g_wohi[D_ * D_];
__device__ __nv_bfloat16 g_wolo[D_ * D_];

// ---------------------------------------------------------------------------
// helpers
// ---------------------------------------------------------------------------
__device__ __forceinline__ uint32_t smem_u32(const void* p) {
    uint32_t a;
    asm("{ .reg .u64 t; cvta.to.shared.u64 t, %1; cvt.u32.u64 %0, t; }"
        : "=r"(a) : "l"(p));
    return a;
}
__device__ __forceinline__ void ldsm_x4(uint32_t* r, uint32_t addr) {
    asm volatile("ldmatrix.sync.aligned.m8n8.x4.shared.b16 {%0,%1,%2,%3}, [%4];"
                 : "=r"(r[0]), "=r"(r[1]), "=r"(r[2]), "=r"(r[3]) : "r"(addr));
}
__device__ __forceinline__ void ldsm_x4t(uint32_t* r, uint32_t addr) {
    asm volatile("ldmatrix.sync.aligned.m8n8.x4.trans.shared.b16 {%0,%1,%2,%3}, [%4];"
                 : "=r"(r[0]), "=r"(r[1]), "=r"(r[2]), "=r"(r[3]) : "r"(addr));
}
__device__ __forceinline__ void mma_bf16(float* c, const uint32_t* a,
                                         const uint32_t* b) {
    asm volatile(
        "mma.sync.aligned.m16n8k16.row.col.f32.bf16.bf16.f32 "
        "{%0,%1,%2,%3}, {%4,%5,%6,%7}, {%8,%9}, {%0,%1,%2,%3};"
        : "+f"(c[0]), "+f"(c[1]), "+f"(c[2]), "+f"(c[3])
        : "r"(a[0]), "r"(a[1]), "r"(a[2]), "r"(a[3]), "r"(b[0]), "r"(b[1]));
}
__device__ __forceinline__ float ex2f(float x) {
    float r;
    asm("ex2.approx.f32 %0, %1;" : "=f"(r) : "f"(x));
    return r;
}
__device__ __forceinline__ uint32_t packbf(float l, float h) {
    uint32_t r;
    asm("cvt.rn.bf16x2.f32 %0, %1, %2;" : "=r"(r) : "f"(h), "f"(l));
    return r;
}
__device__ __forceinline__ float lowf(uint32_t u) { return __uint_as_float(u << 16); }
__device__ __forceinline__ float hif(uint32_t u)  { return __uint_as_float(u & 0xFFFF0000u); }

#define CP_ASYNC16(saddr, gaddr) \
    asm volatile("cp.async.ca.shared.global [%0], [%1], 16;" \
                 :: "r"(saddr), "l"(gaddr) : "memory")
#define CP_COMMIT() asm volatile("cp.async.commit_group;" ::: "memory")
#define CP_WAIT(n)  asm volatile("cp.async.wait_group %0;" :: "n"(n) : "memory")

// ---------------------------------------------------------------------------
// split: fp32 -> (hi bf16, lo bf16)
// ---------------------------------------------------------------------------
__global__ void split_fp32(const float* __restrict__ in,
                           __nv_bfloat16* __restrict__ hi,
                           __nv_bfloat16* __restrict__ lo, int n4) {
    int i = blockIdx.x * blockDim.x + threadIdx.x;
    if (i >= n4) return;
    float4 v = ((const float4*)in)[i];
    uint32_t h0 = packbf(v.x, v.y), h1 = packbf(v.z, v.w);
    uint32_t l0 = packbf(v.x - lowf(h0), v.y - hif(h0));
    uint32_t l1 = packbf(v.z - lowf(h1), v.w - hif(h1));
    ((uint2*)hi)[i] = make_uint2(h0, h1);
    ((uint2*)lo)[i] = make_uint2(l0, l1);
}

// ---------------------------------------------------------------------------
// split-bf16 tensor-core GEMM: C[M,768] = A[M,768] * W[768,768]^T + bias
// CTA 128x128 (R8 config — highest measured tensor%), K-block 32, 8 warps
// (2Mx4N -> warp 64x32), double-buffered cp.async.
// B operands loaded with ldsm_x4 (2 n-tiles per instruction).
// ---------------------------------------------------------------------------
#define GKD    768
#define GROWB  80
#define GOFF_AHI 0
#define GOFF_ALO 10240
#define GOFF_BHI 20480
#define GOFF_BLO 30720
#define GBUF   40960
#define GSMEM_TOTAL (2 * GBUF)

__global__ __launch_bounds__(256)
void gemm_mma_split(const __nv_bfloat16* __restrict__ Ahi,
                    const __nv_bfloat16* __restrict__ Alo,
                    const __nv_bfloat16* __restrict__ Bhi,
                    const __nv_bfloat16* __restrict__ Blo,
                    const float* __restrict__ bias,
                    float* __restrict__ Cf,
                    __nv_bfloat16* __restrict__ Chi,
                    __nv_bfloat16* __restrict__ Clo) {
    extern __shared__ char smc[];
    const uint32_t sb = smem_u32(smc);
    const int tid  = threadIdx.x;
    const int lane = tid & 31;
    const int wid  = tid >> 5;
    const int wm   = wid & 1;
    const int wn   = wid >> 1;
    const int m0 = blockIdx.y * 128;
    const int n0 = blockIdx.x * 128;

    const char* gp[4] = {
        (const char*)(Ahi + (size_t)m0 * GKD),
        (const char*)(Alo + (size_t)m0 * GKD),
        (const char*)(Bhi + (size_t)n0 * GKD),
        (const char*)(Blo + (size_t)n0 * GKD)};
    const uint32_t soff[4] = {GOFF_AHI, GOFF_ALO, GOFF_BHI, GOFF_BLO};

    const int r0c = (tid * 2) >> 2, c0c = (tid * 2) & 3;
    const int r1c = (tid * 2 + 1) >> 2, c1c = (tid * 2 + 1) & 3;

#define GISSUE(kb, buf) do {                                                   \
    const uint32_t bb = sb + (buf) * GBUF;                                     \
    _Pragma("unroll")                                                          \
    for (int mat = 0; mat < 4; mat++) {                                        \
        CP_ASYNC16(bb + soff[mat] + r0c * GROWB + c0c * 16,                    \
                   gp[mat] + (size_t)r0c * (GKD * 2) + (kb) * 64 + c0c * 16);  \
        CP_ASYNC16(bb + soff[mat] + r1c * GROWB + c1c * 16,                    \
                   gp[mat] + (size_t)r1c * (GKD * 2) + (kb) * 64 + c1c * 16);  \
    }                                                                          \
    CP_COMMIT();                                                               \
} while (0)

    float acc[4][4][4];
#pragma unroll
    for (int mt = 0; mt < 4; mt++)
#pragma unroll
        for (int nt = 0; nt < 4; nt++)
#pragma unroll
            for (int k = 0; k < 4; k++) acc[mt][nt][k] = 0.f;

    const uint32_t a_row  = wm * 64 + (lane & 15);
    const uint32_t a_koff = (lane >> 4) << 4;
    // B ldsm_x4 lane mapping: lanes 0-7 -> nt_pair row group 0 / k0-7,
    // 8-15 -> group 0 / k8-15, 16-23 -> group 1 / k0-7, 24-31 -> group 1 / k8-15
    const uint32_t b_row  = wn * 32 + ((lane >> 4) << 3) + (lane & 7);
    const uint32_t b_koff = ((lane >> 3) & 1) << 4;

    GISSUE(0, 0);

    for (int kb = 0; kb < GKD / 32; kb++) {
        const int buf = kb & 1;
        if (kb + 1 < GKD / 32) {
            GISSUE(kb + 1, buf ^ 1);
            CP_WAIT(1);
        } else {
            CP_WAIT(0);
        }
        __syncthreads();

        const uint32_t bb = sb + buf * GBUF;
#pragma unroll
        for (int kk = 0; kk < 2; kk++) {
            const uint32_t ka = kk * 32 + a_koff;
            const uint32_t kbf = kk * 32 + b_koff;
            uint32_t ahi[4][4], alo[4][4], bhi[4][2], blo[4][2];
#pragma unroll
            for (int mt = 0; mt < 4; mt++) {
                ldsm_x4(ahi[mt], bb + GOFF_AHI + (a_row + mt * 16) * GROWB + ka);
                ldsm_x4(alo[mt], bb + GOFF_ALO + (a_row + mt * 16) * GROWB + ka);
            }
#pragma unroll
            for (int p = 0; p < 2; p++) {   // covers nt = 2p, 2p+1
                ldsm_x4(&bhi[2 * p][0],
                        bb + GOFF_BHI + (b_row + p * 16) * GROWB + kbf);
                ldsm_x4(&blo[2 * p][0],
                        bb + GOFF_BLO + (b_row + p * 16) * GROWB + kbf);
            }
#pragma unroll
            for (int mt = 0; mt < 4; mt++)
#pragma unroll
                for (int nt = 0; nt < 4; nt++) {
                    mma_bf16(acc[mt][nt], ahi[mt], bhi[nt]);
                    mma_bf16(acc[mt][nt], ahi[mt], blo[nt]);
                    mma_bf16(acc[mt][nt], alo[mt], bhi[nt]);
                }
        }
        __syncthreads();
    }

    // epilogue
#pragma unroll
    for (int nt = 0; nt < 4; nt++) {
        const int n = n0 + wn * 32 + nt * 8 + (lane & 3) * 2;
        const float b0 = bias[n], b1 = bias[n + 1];
#pragma unroll
        for (int mt = 0; mt < 4; mt++) {
            const int m = m0 + wm * 64 + mt * 16 + (lane >> 2);
            const float v00 = acc[mt][nt][0] + b0, v01 = acc[mt][nt][1] + b1;
            const float v10 = acc[mt][nt][2] + b0, v11 = acc[mt][nt][3] + b1;
            if (Cf) {
                *(float2*)&Cf[(size_t)m * GKD + n] = make_float2(v00, v01);
                *(float2*)&Cf[(size_t)(m + 8) * GKD + n] = make_float2(v10, v11);
            } else {
                uint32_t h0 = packbf(v00, v01);
                uint32_t l0 = packbf(v00 - lowf(h0), v01 - hif(h0));
                uint32_t h1 = packbf(v10, v11);
                uint32_t l1 = packbf(v10 - lowf(h1), v11 - hif(h1));
                *(uint32_t*)&Chi[(size_t)m * GKD + n] = h0;
                *(uint32_t*)&Clo[(size_t)m * GKD + n] = l0;
                *(uint32_t*)&Chi[(size_t)(m + 8) * GKD + n] = h1;
                *(uint32_t*)&Clo[(size_t)(m + 8) * GKD + n] = l1;
            }
        }
    }
#undef GISSUE
}

// ---------------------------------------------------------------------------
// mma.sync flash attention, split-bf16.  K-tile = 64 keys, 2 CTAs/SM
// (R12 config — measured faster than K-tile 128 @ 1 CTA/SM).
// ---------------------------------------------------------------------------
#define APITCH 144
#define ASQH   0
#define ASQL   18432
#define ASK    36864            // + buf*18432 ; lo at +9216
#define ASMEM_TOTAL (36864 + 2 * 18432)

__global__ __launch_bounds__(256, 2)
void attn_mma(const __nv_bfloat16* __restrict__ Khi,
              const __nv_bfloat16* __restrict__ Klo,
              const int* __restrict__ mask,
              __nv_bfloat16* __restrict__ Vhi,
              __nv_bfloat16* __restrict__ Vlo) {
    extern __shared__ char smc[];
    const uint32_t sb = smem_u32(smc);
    const int tid  = threadIdx.x;
    const int lane = tid & 31;
    const int w    = tid >> 5;
    const int q0 = blockIdx.x * 128;
    const int h  = blockIdx.y;
    const int b  = blockIdx.z;

    const size_t gk = ((size_t)b * L_) * D_ + h * DH_;
    const size_t gq = gk + (size_t)q0 * D_;

    const int qrow[4] = {(tid + 0) >> 3, (tid + 256) >> 3,
                         (tid + 512) >> 3, (tid + 768) >> 3};
    const int qcol[4] = {(tid + 0) & 7, (tid + 256) & 7,
                         (tid + 512) & 7, (tid + 768) & 7};
    const int kr0 = tid >> 3,           kc0 = tid & 7;
    const int kr1 = (tid + 256) >> 3,   kc1 = (tid + 256) & 7;

#define AISSUE_K(kt, buf) do {                                                 \
    const uint32_t dh = sb + ASK + (buf) * 18432;                              \
    const __nv_bfloat16* ghx = Khi + gk + (size_t)(kt) * 64 * D_;              \
    const __nv_bfloat16* glx = Klo + gk + (size_t)(kt) * 64 * D_;              \
    const uint32_t s0 = kr0 * APITCH + kc0 * 16;                               \
    const uint32_t s1 = kr1 * APITCH + kc1 * 16;                               \
    const size_t g0 = (size_t)kr0 * D_ + kc0 * 8;                              \
    const size_t g1 = (size_t)kr1 * D_ + kc1 * 8;                              \
    CP_ASYNC16(dh + s0, (const char*)(ghx + g0));                              \
    CP_ASYNC16(dh + s1, (const char*)(ghx + g1));                              \
    CP_ASYNC16(dh + 9216 + s0, (const char*)(glx + g0));                       \
    CP_ASYNC16(dh + 9216 + s1, (const char*)(glx + g1));                       \
    CP_COMMIT();                                                               \
} while (0)

    {
#pragma unroll
        for (int i = 0; i < 4; i++) {
            const uint32_t so = qrow[i] * APITCH + qcol[i] * 16;
            const size_t go = (size_t)qrow[i] * D_ + qcol[i] * 8;
            CP_ASYNC16(sb + ASQH + so, (const char*)(Khi + gq + go));
            CP_ASYNC16(sb + ASQL + so, (const char*)(Klo + gq + go));
        }
        CP_COMMIT();
    }
    AISSUE_K(0, 0);
    AISSUE_K(1, 1);

    CP_WAIT(2);
    __syncthreads();

    uint32_t qh[4][4], ql[4][4];
#pragma unroll
    for (int ks = 0; ks < 4; ks++) {
        const uint32_t a = sb + ASQH + (w * 16 + (lane & 15)) * APITCH +
                           ks * 32 + ((lane >> 4) << 4);
        ldsm_x4(qh[ks], a);
        ldsm_x4(ql[ks], a + 18432);
    }

    const bool rm0 = (__ldg(&mask[b * L_ + q0 + w * 16 + (lane >> 2)]) == 0);
    const bool rm1 = (__ldg(&mask[b * L_ + q0 + w * 16 + (lane >> 2) + 8]) == 0);
    const float kscale = 0.03608439182435161f * 1.4426950408889634f;

    float m0 = -3e38f, m1 = -3e38f, l0 = 0.f, l1 = 0.f;
    float o[8][4];
#pragma unroll
    for (int dn = 0; dn < 8; dn++)
#pragma unroll
        for (int j = 0; j < 4; j++) o[dn][j] = 0.f;

    for (int kt = 0; kt < L_ / 64; kt++) {
        if (kt < L_ / 64 - 1) { CP_WAIT(1); } else { CP_WAIT(0); }
        __syncthreads();
        const uint32_t kb = sb + ASK + (kt & 1) * 18432;

        // ---- S = Q K^T ----
        float s[8][4];
#pragma unroll
        for (int nb = 0; nb < 8; nb++)
#pragma unroll
            for (int j = 0; j < 4; j++) s[nb][j] = 0.f;

#pragma unroll
        for (int nb = 0; nb < 8; nb++) {
            uint32_t bh[8], bl[8];
            const uint32_t a0 = kb + (nb * 8 + (lane & 7)) * APITCH +
                                ((lane >> 3) << 4);
            ldsm_x4(bh, a0);
            ldsm_x4(bh + 4, a0 + 64);
            ldsm_x4(bl, a0 + 9216);
            ldsm_x4(bl + 4, a0 + 9216 + 64);
#pragma unroll
            for (int ks = 0; ks < 4; ks++) {
                mma_bf16(s[nb], qh[ks], bh + ks * 2);
                mma_bf16(s[nb], qh[ks], bl + ks * 2);
                mma_bf16(s[nb], ql[ks], bh + ks * 2);
            }
        }

        // ---- online softmax (exp2 domain) ----
        float tm0 = -3e38f, tm1 = -3e38f;
#pragma unroll
        for (int nb = 0; nb < 8; nb++) {
            s[nb][0] = rm0 ? -1e9f : s[nb][0] * kscale;
            s[nb][1] = rm0 ? -1e9f : s[nb][1] * kscale;
            s[nb][2] = rm1 ? -1e9f : s[nb][2] * kscale;
            s[nb][3] = rm1 ? -1e9f : s[nb][3] * kscale;
            tm0 = fmaxf(tm0, fmaxf(s[nb][0], s[nb][1]));
            tm1 = fmaxf(tm1, fmaxf(s[nb][2], s[nb][3]));
        }
        tm0 = fmaxf(tm0, __shfl_xor_sync(0xffffffffu, tm0, 1));
        tm0 = fmaxf(tm0, __shfl_xor_sync(0xffffffffu, tm0, 2));
        tm1 = fmaxf(tm1, __shfl_xor_sync(0xffffffffu, tm1, 1));
        tm1 = fmaxf(tm1, __shfl_xor_sync(0xffffffffu, tm1, 2));
        const float nm0 = fmaxf(m0, tm0), nm1 = fmaxf(m1, tm1);
        const float c0 = ex2f(m0 - nm0), c1 = ex2f(m1 - nm1);
        m0 = nm0; m1 = nm1;

        float ts0 = 0.f, ts1 = 0.f;
#pragma unroll
        for (int nb = 0; nb < 8; nb++) {
            s[nb][0] = ex2f(s[nb][0] - nm0);
            s[nb][1] = ex2f(s[nb][1] - nm0);
            s[nb][2] = ex2f(s[nb][2] - nm1);
            s[nb][3] = ex2f(s[nb][3] - nm1);
            ts0 += s[nb][0] + s[nb][1];
            ts1 += s[nb][2] + s[nb][3];
        }
        l0 = l0 * c0 + ts0;
        l1 = l1 * c1 + ts1;
#pragma unroll
        for (int dn = 0; dn < 8; dn++) {
            o[dn][0] *= c0; o[dn][1] *= c0;
            o[dn][2] *= c1; o[dn][3] *= c1;
        }

        // ---- O += P @ V (V = K tile) ----
#pragma unroll
        for (int kk = 0; kk < 4; kk++) {
            uint32_t ph[4], pl[4];
            {
                const float* sA = s[kk * 2];
                const float* sB = s[kk * 2 + 1];
                ph[0] = packbf(sA[0], sA[1]);
                ph[1] = packbf(sA[2], sA[3]);
                ph[2] = packbf(sB[0], sB[1]);
                ph[3] = packbf(sB[2], sB[3]);
                pl[0] = packbf(sA[0] - lowf(ph[0]), sA[1] - hif(ph[0]));
                pl[1] = packbf(sA[2] - lowf(ph[1]), sA[3] - hif(ph[1]));
                pl[2] = packbf(sB[0] - lowf(ph[2]), sB[1] - hif(ph[2]));
                pl[3] = packbf(sB[2] - lowf(ph[3]), sB[3] - hif(ph[3]));
            }
#pragma unroll
            for (int dn2 = 0; dn2 < 4; dn2++) {
                uint32_t vh[4], vl[4];
                const uint32_t a = kb + (kk * 16 + (lane & 15)) * APITCH +
                                   dn2 * 32 + ((lane >> 4) << 4);
                ldsm_x4t(vh, a);
                ldsm_x4t(vl, a + 9216);
                mma_bf16(o[dn2 * 2],     ph, vh);
                mma_bf16(o[dn2 * 2],     ph, vl);
                mma_bf16(o[dn2 * 2],     pl, vh);
                mma_bf16(o[dn2 * 2 + 1], ph, vh + 2);
                mma_bf16(o[dn2 * 2 + 1], ph, vl + 2);
                mma_bf16(o[dn2 * 2 + 1], pl, vh + 2);
            }
        }

        __syncthreads();
        if (kt + 2 < L_ / 64) AISSUE_K(kt + 2, kt & 1);
    }

    // ---- epilogue: normalize, split to bf16, store ----
    l0 += __shfl_xor_sync(0xffffffffu, l0, 1);
    l0 += __shfl_xor_sync(0xffffffffu, l0, 2);
    l1 += __shfl_xor_sync(0xffffffffu, l1, 1);
    l1 += __shfl_xor_sync(0xffffffffu, l1, 2);
    const float inv0 = 1.0f / l0, inv1 = 1.0f / l1;
    const int qa = q0 + w * 16 + (lane >> 2);
    const size_t ra = ((size_t)b * L_ + qa) * D_ + h * DH_;
    const size_t rb = ra + (size_t)8 * D_;
#pragma unroll
    for (int dn = 0; dn < 8; dn++) {
        const int col = dn * 8 + (lane & 3) * 2;
        const float v0 = o[dn][0] * inv0, v1 = o[dn][1] * inv0;
        const float v2 = o[dn][2] * inv1, v3 = o[dn][3] * inv1;
        uint32_t h0 = packbf(v0, v1);
        uint32_t l0p = packbf(v0 - lowf(h0), v1 - hif(h0));
        uint32_t h1 = packbf(v2, v3);
        uint32_t l1p = packbf(v2 - lowf(h1), v3 - hif(h1));
        *(uint32_t*)&Vhi[ra + col] = h0;
        *(uint32_t*)&Vlo[ra + col] = l0p;
        *(uint32_t*)&Vhi[rb + col] = h1;
        *(uint32_t*)&Vlo[rb + col] = l1p;
    }
#undef AISSUE_K
}

// ---------------------------------------------------------------------------
// Launch. Inputs: 0:x 1:mask 2:Wq 3:bq 4:Wk 5:bk 6:Wv 7:bv 8:Wo 9:bo
// (Q projection and Wv/bv are dead in the reference: V = K, scores = K K^T.)
// ---------------------------------------------------------------------------
extern "C" void kernel_launch(void* const* d_in, const int* in_sizes, int n_in,
                              void* d_out, int out_size) {
    const float* x    = (const float*)d_in[0];
    const int*   mask = (const int*)  d_in[1];
    const float* Wk   = (const float*)d_in[4];
    const float* bk   = (const float*)d_in[5];
    const float* Wo   = (const float*)d_in[8];
    const float* bo   = (const float*)d_in[9];
    float* out = (float*)d_out;

    __nv_bfloat16 *pxhi, *pxlo, *pkhi, *pklo, *pvhi, *pvlo;
    __nv_bfloat16 *pwkhi, *pwklo, *pwohi, *pwolo;
    cudaGetSymbolAddress((void**)&pxhi,  g_xhi);
    cudaGetSymbolAddress((void**)&pxlo,  g_xlo);
    cudaGetSymbolAddress((void**)&pkhi,  g_khi);
    cudaGetSymbolAddress((void**)&pklo,  g_klo);
    cudaGetSymbolAddress((void**)&pvhi,  g_vhi);
    cudaGetSymbolAddress((void**)&pvlo,  g_vlo);
    cudaGetSymbolAddress((void**)&pwkhi, g_wkhi);
    cudaGetSymbolAddress((void**)&pwklo, g_wklo);
    cudaGetSymbolAddress((void**)&pwohi, g_wohi);
    cudaGetSymbolAddress((void**)&pwolo, g_wolo);

    cudaFuncSetAttribute(gemm_mma_split,
                         cudaFuncAttributeMaxDynamicSharedMemorySize,
                         GSMEM_TOTAL);
    cudaFuncSetAttribute(attn_mma,
                         cudaFuncAttributeMaxDynamicSharedMemorySize,
                         ASMEM_TOTAL);

    const int M = B_ * L_;                    // 8192
    const int nx4 = M * D_ / 4;
    const int nw4 = D_ * D_ / 4;

    split_fp32<<<(nx4 + 255) / 256, 256>>>(x,  pxhi,  pxlo,  nx4);
    split_fp32<<<(nw4 + 255) / 256, 256>>>(Wk, pwkhi, pwklo, nw4);
    split_fp32<<<(nw4 + 255) / 256, 256>>>(Wo, pwohi, pwolo, nw4);

    // 1) K = x @ Wk^T + bk  -> split bf16
    {
        dim3 grid(D_ / 128, M / 128);
        gemm_mma_split<<<grid, 256, GSMEM_TOTAL>>>(pxhi, pxlo, pwkhi, pwklo,
                                                   bk, nullptr, pkhi, pklo);
    }
    // 2) fused flash attention on tensor cores -> split bf16 output
    {
        dim3 grid(L_ / 128, H_, B_);
        attn_mma<<<grid, 256, ASMEM_TOTAL>>>(pkhi, pklo, mask, pvhi, pvlo);
    }
    // 3) out = wV @ Wo^T + bo  -> fp32
    {
        dim3 grid(D_ / 128, M / 128);
        gemm_mma_split<<<grid, 256, GSMEM_TOTAL>>>(pvhi, pvlo, pwohi, pwolo,
                                                   bo, out, nullptr, nullptr);
    }
}

// round 14
// speedup vs baseline: 1.5431x; 1.3877x over previous
#include <cuda_runtime.h>
#include <cuda_fp16.h>
#include <cstdint>

#define B_  8
#define L_  1024
#define D_  768
#define H_  12
#define DH_ 64

// ---------------- scratch (__device__ globals; no allocation allowed) ------
// fp16 2-term scheme: A-side operands 1 limb (hi), B-side operands 2 limbs.
__device__ __half g_xhi [B_ * L_ * D_];   // x, 1 limb (GEMM1 A-side)
__device__ __half g_khi [B_ * L_ * D_];   // K projection hi (attn Q/K/V)
__device__ __half g_klo [B_ * L_ * D_];   // K projection lo (attn B-side)
__device__ __half g_vhi [B_ * L_ * D_];   // attention output, 1 limb (GEMM2 A)
__device__ __half g_wkhi[D_ * D_];        // Wk 2 limbs (B-side)
__device__ __half g_wklo[D_ * D_];
__device__ __half g_wohi[D_ * D_];        // Wo 2 limbs (B-side)
__device__ __half g_wolo[D_ * D_];

// ---------------------------------------------------------------------------
// helpers
// ---------------------------------------------------------------------------
__device__ __forceinline__ uint32_t smem_u32(const void* p) {
    uint32_t a;
    asm("{ .reg .u64 t; cvta.to.shared.u64 t, %1; cvt.u32.u64 %0, t; }"
        : "=r"(a) : "l"(p));
    return a;
}
__device__ __forceinline__ void ldsm_x4(uint32_t* r, uint32_t addr) {
    asm volatile("ldmatrix.sync.aligned.m8n8.x4.shared.b16 {%0,%1,%2,%3}, [%4];"
                 : "=r"(r[0]), "=r"(r[1]), "=r"(r[2]), "=r"(r[3]) : "r"(addr));
}
__device__ __forceinline__ void ldsm_x4t(uint32_t* r, uint32_t addr) {
    asm volatile("ldmatrix.sync.aligned.m8n8.x4.trans.shared.b16 {%0,%1,%2,%3}, [%4];"
                 : "=r"(r[0]), "=r"(r[1]), "=r"(r[2]), "=r"(r[3]) : "r"(addr));
}
__device__ __forceinline__ void mma_f16(float* c, const uint32_t* a,
                                        const uint32_t* b) {
    asm volatile(
        "mma.sync.aligned.m16n8k16.row.col.f32.f16.f16.f32 "
        "{%0,%1,%2,%3}, {%4,%5,%6,%7}, {%8,%9}, {%0,%1,%2,%3};"
        : "+f"(c[0]), "+f"(c[1]), "+f"(c[2]), "+f"(c[3])
        : "r"(a[0]), "r"(a[1]), "r"(a[2]), "r"(a[3]), "r"(b[0]), "r"(b[1]));
}
__device__ __forceinline__ float ex2f(float x) {
    float r;
    asm("ex2.approx.f32 %0, %1;" : "=f"(r) : "f"(x));
    return r;
}
// pack two fp32 into f16x2: low half = l, high half = h
__device__ __forceinline__ uint32_t packh(float l, float h) {
    uint32_t r;
    asm("cvt.rn.f16x2.f32 %0, %1, %2;" : "=r"(r) : "f"(h), "f"(l));
    return r;
}
__device__ __forceinline__ float lowh(uint32_t u) {
    float f;
    asm("{ .reg .b16 lo, hi; mov.b32 {lo, hi}, %1; cvt.f32.f16 %0, lo; }"
        : "=f"(f) : "r"(u));
    return f;
}
__device__ __forceinline__ float hih(uint32_t u) {
    float f;
    asm("{ .reg .b16 lo, hi; mov.b32 {lo, hi}, %1; cvt.f32.f16 %0, hi; }"
        : "=f"(f) : "r"(u));
    return f;
}

#define CP_ASYNC16(saddr, gaddr) \
    asm volatile("cp.async.ca.shared.global [%0], [%1], 16;" \
                 :: "r"(saddr), "l"(gaddr) : "memory")
#define CP_COMMIT() asm volatile("cp.async.commit_group;" ::: "memory")
#define CP_WAIT(n)  asm volatile("cp.async.wait_group %0;" :: "n"(n) : "memory")

// ---------------------------------------------------------------------------
// weight split: fp32 -> (hi fp16, lo fp16);  x convert: fp32 -> hi fp16 only
// ---------------------------------------------------------------------------
__global__ void split_w(const float* __restrict__ in,
                        __half* __restrict__ hi,
                        __half* __restrict__ lo, int n4) {
    int i = blockIdx.x * blockDim.x + threadIdx.x;
    if (i >= n4) return;
    float4 v = ((const float4*)in)[i];
    uint32_t h0 = packh(v.x, v.y), h1 = packh(v.z, v.w);
    uint32_t l0 = packh(v.x - lowh(h0), v.y - hih(h0));
    uint32_t l1 = packh(v.z - lowh(h1), v.w - hih(h1));
    ((uint2*)hi)[i] = make_uint2(h0, h1);
    ((uint2*)lo)[i] = make_uint2(l0, l1);
}
__global__ void conv_x(const float* __restrict__ in,
                       __half* __restrict__ hi, int n4) {
    int i = blockIdx.x * blockDim.x + threadIdx.x;
    if (i >= n4) return;
    float4 v = ((const float4*)in)[i];
    ((uint2*)hi)[i] = make_uint2(packh(v.x, v.y), packh(v.z, v.w));
}

// ---------------------------------------------------------------------------
// fp16 2-term tensor-core GEMM: C[M,768] = A[M,768] * W[768,768]^T + bias
// A 1-limb, W 2-limb:  C = Ahi*Whi + Ahi*Wlo   (drops Alo*W, ~2^-12)
// CTA 128x128, K-block 32, 8 warps (2Mx4N), double-buffered cp.async.
// ---------------------------------------------------------------------------
#define GKD    768
#define GROWB  80
#define GOFF_AHI 0
#define GOFF_BHI 10240
#define GOFF_BLO 20480
#define GBUF   30720
#define GSMEM_TOTAL (2 * GBUF)

__global__ __launch_bounds__(256)
void gemm_mma_2t(const __half* __restrict__ Ahi,
                 const __half* __restrict__ Bhi,
                 const __half* __restrict__ Blo,
                 const float* __restrict__ bias,
                 float* __restrict__ Cf,
                 __half* __restrict__ Chi,
                 __half* __restrict__ Clo) {
    extern __shared__ char smc[];
    const uint32_t sb = smem_u32(smc);
    const int tid  = threadIdx.x;
    const int lane = tid & 31;
    const int wid  = tid >> 5;
    const int wm   = wid & 1;
    const int wn   = wid >> 1;
    const int m0 = blockIdx.y * 128;
    const int n0 = blockIdx.x * 128;

    const char* gp[3] = {
        (const char*)(Ahi + (size_t)m0 * GKD),
        (const char*)(Bhi + (size_t)n0 * GKD),
        (const char*)(Blo + (size_t)n0 * GKD)};
    const uint32_t soff[3] = {GOFF_AHI, GOFF_BHI, GOFF_BLO};

    const int r0c = (tid * 2) >> 2, c0c = (tid * 2) & 3;
    const int r1c = (tid * 2 + 1) >> 2, c1c = (tid * 2 + 1) & 3;

#define GISSUE(kb, buf) do {                                                   \
    const uint32_t bb = sb + (buf) * GBUF;                                     \
    _Pragma("unroll")                                                          \
    for (int mat = 0; mat < 3; mat++) {                                        \
        CP_ASYNC16(bb + soff[mat] + r0c * GROWB + c0c * 16,                    \
                   gp[mat] + (size_t)r0c * (GKD * 2) + (kb) * 64 + c0c * 16);  \
        CP_ASYNC16(bb + soff[mat] + r1c * GROWB + c1c * 16,                    \
                   gp[mat] + (size_t)r1c * (GKD * 2) + (kb) * 64 + c1c * 16);  \
    }                                                                          \
    CP_COMMIT();                                                               \
} while (0)

    float acc[4][4][4];
#pragma unroll
    for (int mt = 0; mt < 4; mt++)
#pragma unroll
        for (int nt = 0; nt < 4; nt++)
#pragma unroll
            for (int k = 0; k < 4; k++) acc[mt][nt][k] = 0.f;

    const uint32_t a_row  = wm * 64 + (lane & 15);
    const uint32_t a_koff = (lane >> 4) << 4;
    // paired B ldsm_x4: lanes 0-15 first 8-row group, 16-31 second
    const uint32_t b_row  = wn * 32 + ((lane >> 4) << 3) + (lane & 7);
    const uint32_t b_koff = ((lane >> 3) & 1) << 4;

    GISSUE(0, 0);

    for (int kb = 0; kb < GKD / 32; kb++) {
        const int buf = kb & 1;
        if (kb + 1 < GKD / 32) {
            GISSUE(kb + 1, buf ^ 1);
            CP_WAIT(1);
        } else {
            CP_WAIT(0);
        }
        __syncthreads();

        const uint32_t bb = sb + buf * GBUF;
#pragma unroll
        for (int kk = 0; kk < 2; kk++) {
            const uint32_t ka = kk * 32 + a_koff;
            const uint32_t kbf = kk * 32 + b_koff;
            uint32_t ahi[4][4], bhi[4][2], blo[4][2];
#pragma unroll
            for (int mt = 0; mt < 4; mt++)
                ldsm_x4(ahi[mt], bb + GOFF_AHI + (a_row + mt * 16) * GROWB + ka);
#pragma unroll
            for (int p = 0; p < 2; p++) {
                ldsm_x4(&bhi[2 * p][0],
                        bb + GOFF_BHI + (b_row + p * 16) * GROWB + kbf);
                ldsm_x4(&blo[2 * p][0],
                        bb + GOFF_BLO + (b_row + p * 16) * GROWB + kbf);
            }
#pragma unroll
            for (int mt = 0; mt < 4; mt++)
#pragma unroll
                for (int nt = 0; nt < 4; nt++) {
                    mma_f16(acc[mt][nt], ahi[mt], bhi[nt]);
                    mma_f16(acc[mt][nt], ahi[mt], blo[nt]);
                }
        }
        __syncthreads();
    }

    // epilogue: +bias, write fp32 or fp16 2-limb
#pragma unroll
    for (int nt = 0; nt < 4; nt++) {
        const int n = n0 + wn * 32 + nt * 8 + (lane & 3) * 2;
        const float b0 = bias[n], b1 = bias[n + 1];
#pragma unroll
        for (int mt = 0; mt < 4; mt++) {
            const int m = m0 + wm * 64 + mt * 16 + (lane >> 2);
            const float v00 = acc[mt][nt][0] + b0, v01 = acc[mt][nt][1] + b1;
            const float v10 = acc[mt][nt][2] + b0, v11 = acc[mt][nt][3] + b1;
            if (Cf) {
                *(float2*)&Cf[(size_t)m * GKD + n] = make_float2(v00, v01);
                *(float2*)&Cf[(size_t)(m + 8) * GKD + n] = make_float2(v10, v11);
            } else {
                uint32_t h0 = packh(v00, v01);
                uint32_t l0 = packh(v00 - lowh(h0), v01 - hih(h0));
                uint32_t h1 = packh(v10, v11);
                uint32_t l1 = packh(v10 - lowh(h1), v11 - hih(h1));
                *(uint32_t*)&Chi[(size_t)m * GKD + n] = h0;
                *(uint32_t*)&Clo[(size_t)m * GKD + n] = l0;
                *(uint32_t*)&Chi[(size_t)(m + 8) * GKD + n] = h1;
                *(uint32_t*)&Clo[(size_t)(m + 8) * GKD + n] = l1;
            }
        }
    }
#undef GISSUE
}

// ---------------------------------------------------------------------------
// fp16 2-term flash attention.  Q 1-limb (=Khi), K-tile 2-limb, P 1-limb,
// V 2-limb:  S = Qhi*(Khi+Klo);  O = Phi*(Vhi+Vlo).
// K-tile = 64 keys, 2 CTAs/SM, double-buffered cp.async.
// ---------------------------------------------------------------------------
#define APITCH 144
#define ASQH   0
#define ASK    18432            // + buf*18432 ; lo at +9216
#define ASMEM_TOTAL (18432 + 2 * 18432)

__global__ __launch_bounds__(256, 2)
void attn_mma(const __half* __restrict__ Khi,
              const __half* __restrict__ Klo,
              const int* __restrict__ mask,
              __half* __restrict__ Vout) {
    extern __shared__ char smc[];
    const uint32_t sb = smem_u32(smc);
    const int tid  = threadIdx.x;
    const int lane = tid & 31;
    const int w    = tid >> 5;
    const int q0 = blockIdx.x * 128;
    const int h  = blockIdx.y;
    const int b  = blockIdx.z;

    const size_t gk = ((size_t)b * L_) * D_ + h * DH_;
    const size_t gq = gk + (size_t)q0 * D_;

    const int qrow[4] = {(tid + 0) >> 3, (tid + 256) >> 3,
                         (tid + 512) >> 3, (tid + 768) >> 3};
    const int qcol[4] = {(tid + 0) & 7, (tid + 256) & 7,
                         (tid + 512) & 7, (tid + 768) & 7};
    const int kr0 = tid >> 3,           kc0 = tid & 7;
    const int kr1 = (tid + 256) >> 3,   kc1 = (tid + 256) & 7;

#define AISSUE_K(kt, buf) do {                                                 \
    const uint32_t dh = sb + ASK + (buf) * 18432;                              \
    const __half* ghx = Khi + gk + (size_t)(kt) * 64 * D_;                     \
    const __half* glx = Klo + gk + (size_t)(kt) * 64 * D_;                     \
    const uint32_t s0 = kr0 * APITCH + kc0 * 16;                               \
    const uint32_t s1 = kr1 * APITCH + kc1 * 16;                               \
    const size_t g0 = (size_t)kr0 * D_ + kc0 * 8;                              \
    const size_t g1 = (size_t)kr1 * D_ + kc1 * 8;                              \
    CP_ASYNC16(dh + s0, (const char*)(ghx + g0));                              \
    CP_ASYNC16(dh + s1, (const char*)(ghx + g1));                              \
    CP_ASYNC16(dh + 9216 + s0, (const char*)(glx + g0));                       \
    CP_ASYNC16(dh + 9216 + s1, (const char*)(glx + g1));                       \
    CP_COMMIT();                                                               \
} while (0)

    {
#pragma unroll
        for (int i = 0; i < 4; i++) {
            const uint32_t so = qrow[i] * APITCH + qcol[i] * 16;
            const size_t go = (size_t)qrow[i] * D_ + qcol[i] * 8;
            CP_ASYNC16(sb + ASQH + so, (const char*)(Khi + gq + go));
        }
        CP_COMMIT();
    }
    AISSUE_K(0, 0);
    AISSUE_K(1, 1);

    CP_WAIT(2);
    __syncthreads();

    uint32_t qh[4][4];
#pragma unroll
    for (int ks = 0; ks < 4; ks++) {
        const uint32_t a = sb + ASQH + (w * 16 + (lane & 15)) * APITCH +
                           ks * 32 + ((lane >> 4) << 4);
        ldsm_x4(qh[ks], a);
    }

    const bool rm0 = (__ldg(&mask[b * L_ + q0 + w * 16 + (lane >> 2)]) == 0);
    const bool rm1 = (__ldg(&mask[b * L_ + q0 + w * 16 + (lane >> 2) + 8]) == 0);
    const float kscale = 0.03608439182435161f * 1.4426950408889634f;

    float m0 = -3e38f, m1 = -3e38f, l0 = 0.f, l1 = 0.f;
    float o[8][4];
#pragma unroll
    for (int dn = 0; dn < 8; dn++)
#pragma unroll
        for (int j = 0; j < 4; j++) o[dn][j] = 0.f;

    for (int kt = 0; kt < L_ / 64; kt++) {
        if (kt < L_ / 64 - 1) { CP_WAIT(1); } else { CP_WAIT(0); }
        __syncthreads();
        const uint32_t kb = sb + ASK + (kt & 1) * 18432;

        // ---- S = Qhi * (Khi + Klo) ----
        float s[8][4];
#pragma unroll
        for (int nb = 0; nb < 8; nb++)
#pragma unroll
            for (int j = 0; j < 4; j++) s[nb][j] = 0.f;

#pragma unroll
        for (int nb = 0; nb < 8; nb++) {
            uint32_t bh[8], bl[8];
            const uint32_t a0 = kb + (nb * 8 + (lane & 7)) * APITCH +
                                ((lane >> 3) << 4);
            ldsm_x4(bh, a0);
            ldsm_x4(bh + 4, a0 + 64);
            ldsm_x4(bl, a0 + 9216);
            ldsm_x4(bl + 4, a0 + 9216 + 64);
#pragma unroll
            for (int ks = 0; ks < 4; ks++) {
                mma_f16(s[nb], qh[ks], bh + ks * 2);
                mma_f16(s[nb], qh[ks], bl + ks * 2);
            }
        }

        // ---- online softmax (exp2 domain) ----
        float tm0 = -3e38f, tm1 = -3e38f;
#pragma unroll
        for (int nb = 0; nb < 8; nb++) {
            s[nb][0] = rm0 ? -1e9f : s[nb][0] * kscale;
            s[nb][1] = rm0 ? -1e9f : s[nb][1] * kscale;
            s[nb][2] = rm1 ? -1e9f : s[nb][2] * kscale;
            s[nb][3] = rm1 ? -1e9f : s[nb][3] * kscale;
            tm0 = fmaxf(tm0, fmaxf(s[nb][0], s[nb][1]));
            tm1 = fmaxf(tm1, fmaxf(s[nb][2], s[nb][3]));
        }
        tm0 = fmaxf(tm0, __shfl_xor_sync(0xffffffffu, tm0, 1));
        tm0 = fmaxf(tm0, __shfl_xor_sync(0xffffffffu, tm0, 2));
        tm1 = fmaxf(tm1, __shfl_xor_sync(0xffffffffu, tm1, 1));
        tm1 = fmaxf(tm1, __shfl_xor_sync(0xffffffffu, tm1, 2));
        const float nm0 = fmaxf(m0, tm0), nm1 = fmaxf(m1, tm1);
        const float c0 = ex2f(m0 - nm0), c1 = ex2f(m1 - nm1);
        m0 = nm0; m1 = nm1;

        float ts0 = 0.f, ts1 = 0.f;
#pragma unroll
        for (int nb = 0; nb < 8; nb++) {
            s[nb][0] = ex2f(s[nb][0] - nm0);
            s[nb][1] = ex2f(s[nb][1] - nm0);
            s[nb][2] = ex2f(s[nb][2] - nm1);
            s[nb][3] = ex2f(s[nb][3] - nm1);
            ts0 += s[nb][0] + s[nb][1];
            ts1 += s[nb][2] + s[nb][3];
        }
        l0 = l0 * c0 + ts0;
        l1 = l1 * c1 + ts1;
#pragma unroll
        for (int dn = 0; dn < 8; dn++) {
            o[dn][0] *= c0; o[dn][1] *= c0;
            o[dn][2] *= c1; o[dn][3] *= c1;
        }

        // ---- O += Phi * (Vhi + Vlo), V = K tile ----
#pragma unroll
        for (int kk = 0; kk < 4; kk++) {
            uint32_t ph[4];
            {
                const float* sA = s[kk * 2];
                const float* sB = s[kk * 2 + 1];
                ph[0] = packh(sA[0], sA[1]);
                ph[1] = packh(sA[2], sA[3]);
                ph[2] = packh(sB[0], sB[1]);
                ph[3] = packh(sB[2], sB[3]);
            }
#pragma unroll
            for (int dn2 = 0; dn2 < 4; dn2++) {
                uint32_t vh[4], vl[4];
                const uint32_t a = kb + (kk * 16 + (lane & 15)) * APITCH +
                                   dn2 * 32 + ((lane >> 4) << 4);
                ldsm_x4t(vh, a);
                ldsm_x4t(vl, a + 9216);
                mma_f16(o[dn2 * 2],     ph, vh);
                mma_f16(o[dn2 * 2],     ph, vl);
                mma_f16(o[dn2 * 2 + 1], ph, vh + 2);
                mma_f16(o[dn2 * 2 + 1], ph, vl + 2);
            }
        }

        __syncthreads();
        if (kt + 2 < L_ / 64) AISSUE_K(kt + 2, kt & 1);
    }

    // ---- epilogue: normalize, store 1-limb fp16 ----
    l0 += __shfl_xor_sync(0xffffffffu, l0, 1);
    l0 += __shfl_xor_sync(0xffffffffu, l0, 2);
    l1 += __shfl_xor_sync(0xffffffffu, l1, 1);
    l1 += __shfl_xor_sync(0xffffffffu, l1, 2);
    const float inv0 = 1.0f / l0, inv1 = 1.0f / l1;
    const int qa = q0 + w * 16 + (lane >> 2);
    const size_t ra = ((size_t)b * L_ + qa) * D_ + h * DH_;
    const size_t rb = ra + (size_t)8 * D_;
#pragma unroll
    for (int dn = 0; dn < 8; dn++) {
        const int col = dn * 8 + (lane & 3) * 2;
        *(uint32_t*)&Vout[ra + col] = packh(o[dn][0] * inv0, o[dn][1] * inv0);
        *(uint32_t*)&Vout[rb + col] = packh(o[dn][2] * inv1, o[dn][3] * inv1);
    }
#undef AISSUE_K
}

// ---------------------------------------------------------------------------
// Launch. Inputs: 0:x 1:mask 2:Wq 3:bq 4:Wk 5:bk 6:Wv 7:bv 8:Wo 9:bo
// (Q projection and Wv/bv are dead in the reference: V = K, scores = K K^T.)
// ---------------------------------------------------------------------------
extern "C" void kernel_launch(void* const* d_in, const int* in_sizes, int n_in,
                              void* d_out, int out_size) {
    const float* x    = (const float*)d_in[0];
    const int*   mask = (const int*)  d_in[1];
    const float* Wk   = (const float*)d_in[4];
    const float* bk   = (const float*)d_in[5];
    const float* Wo   = (const float*)d_in[8];
    const float* bo   = (const float*)d_in[9];
    float* out = (float*)d_out;

    __half *pxhi, *pkhi, *pklo, *pvhi, *pwkhi, *pwklo, *pwohi, *pwolo;
    cudaGetSymbolAddress((void**)&pxhi,  g_xhi);
    cudaGetSymbolAddress((void**)&pkhi,  g_khi);
    cudaGetSymbolAddress((void**)&pklo,  g_klo);
    cudaGetSymbolAddress((void**)&pvhi,  g_vhi);
    cudaGetSymbolAddress((void**)&pwkhi, g_wkhi);
    cudaGetSymbolAddress((void**)&pwklo, g_wklo);
    cudaGetSymbolAddress((void**)&pwohi, g_wohi);
    cudaGetSymbolAddress((void**)&pwolo, g_wolo);

    cudaFuncSetAttribute(gemm_mma_2t,
                         cudaFuncAttributeMaxDynamicSharedMemorySize,
                         GSMEM_TOTAL);
    cudaFuncSetAttribute(attn_mma,
                         cudaFuncAttributeMaxDynamicSharedMemorySize,
                         ASMEM_TOTAL);

    const int M = B_ * L_;                    // 8192
    const int nx4 = M * D_ / 4;
    const int nw4 = D_ * D_ / 4;

    conv_x <<<(nx4 + 255) / 256, 256>>>(x,  pxhi,  nx4);
    split_w<<<(nw4 + 255) / 256, 256>>>(Wk, pwkhi, pwklo, nw4);
    split_w<<<(nw4 + 255) / 256, 256>>>(Wo, pwohi, pwolo, nw4);

    // 1) K = x @ Wk^T + bk  -> fp16 2-limb
    {
        dim3 grid(D_ / 128, M / 128);
        gemm_mma_2t<<<grid, 256, GSMEM_TOTAL>>>(pxhi, pwkhi, pwklo,
                                                bk, nullptr, pkhi, pklo);
    }
    // 2) fused flash attention -> fp16 1-limb
    {
        dim3 grid(L_ / 128, H_, B_);
        attn_mma<<<grid, 256, ASMEM_TOTAL>>>(pkhi, pklo, mask, pvhi);
    }
    // 3) out = wV @ Wo^T + bo  -> fp32
    {
        dim3 grid(D_ / 128, M / 128);
        gemm_mma_2t<<<grid, 256, GSMEM_TOTAL>>>(pvhi, pwohi, pwolo,
                                                bo, out, nullptr, nullptr);
    }
}

// round 17
// speedup vs baseline: 1.5656x; 1.0146x over previous
#include <cuda_runtime.h>
#include <cuda_fp16.h>
#include <cstdint>

#define B_  8
#define L_  1024
#define D_  768
#define H_  12
#define DH_ 64

// ---------------- scratch (__device__ globals; no allocation allowed) ------
// fp16 2-term scheme: A-side operands 1 limb (hi), B-side operands 2 limbs.
__device__ __half g_xhi [B_ * L_ * D_];   // x, 1 limb (GEMM1 A-side)
__device__ __half g_khi [B_ * L_ * D_];   // K projection hi (attn Q/K/V)
__device__ __half g_klo [B_ * L_ * D_];   // K projection lo (attn B-side)
__device__ __half g_vhi [B_ * L_ * D_];   // attention output, 1 limb (GEMM2 A)
__device__ __half g_wkhi[D_ * D_];        // Wk 2 limbs (B-side)
__device__ __half g_wklo[D_ * D_];
__device__ __half g_wohi[D_ * D_];        // Wo 2 limbs (B-side)
__device__ __half g_wolo[D_ * D_];

// ---------------------------------------------------------------------------
// helpers
// ---------------------------------------------------------------------------
__device__ __forceinline__ uint32_t smem_u32(const void* p) {
    uint32_t a;
    asm("{ .reg .u64 t; cvta.to.shared.u64 t, %1; cvt.u32.u64 %0, t; }"
        : "=r"(a) : "l"(p));
    return a;
}
__device__ __forceinline__ void ldsm_x4(uint32_t* r, uint32_t addr) {
    asm volatile("ldmatrix.sync.aligned.m8n8.x4.shared.b16 {%0,%1,%2,%3}, [%4];"
                 : "=r"(r[0]), "=r"(r[1]), "=r"(r[2]), "=r"(r[3]) : "r"(addr));
}
__device__ __forceinline__ void ldsm_x4t(uint32_t* r, uint32_t addr) {
    asm volatile("ldmatrix.sync.aligned.m8n8.x4.trans.shared.b16 {%0,%1,%2,%3}, [%4];"
                 : "=r"(r[0]), "=r"(r[1]), "=r"(r[2]), "=r"(r[3]) : "r"(addr));
}
__device__ __forceinline__ void mma_f16(float* c, const uint32_t* a,
                                        const uint32_t* b) {
    asm volatile(
        "mma.sync.aligned.m16n8k16.row.col.f32.f16.f16.f32 "
        "{%0,%1,%2,%3}, {%4,%5,%6,%7}, {%8,%9}, {%0,%1,%2,%3};"
        : "+f"(c[0]), "+f"(c[1]), "+f"(c[2]), "+f"(c[3])
        : "r"(a[0]), "r"(a[1]), "r"(a[2]), "r"(a[3]), "r"(b[0]), "r"(b[1]));
}
__device__ __forceinline__ float ex2f(float x) {
    float r;
    asm("ex2.approx.f32 %0, %1;" : "=f"(r) : "f"(x));
    return r;
}
// pack two fp32 into f16x2: low half = l, high half = h
__device__ __forceinline__ uint32_t packh(float l, float h) {
    uint32_t r;
    asm("cvt.rn.f16x2.f32 %0, %1, %2;" : "=r"(r) : "f"(h), "f"(l));
    return r;
}
__device__ __forceinline__ float lowh(uint32_t u) {
    float f;
    asm("{ .reg .b16 lo, hi; mov.b32 {lo, hi}, %1; cvt.f32.f16 %0, lo; }"
        : "=f"(f) : "r"(u));
    return f;
}
__device__ __forceinline__ float hih(uint32_t u) {
    float f;
    asm("{ .reg .b16 lo, hi; mov.b32 {lo, hi}, %1; cvt.f32.f16 %0, hi; }"
        : "=f"(f) : "r"(u));
    return f;
}

#define CP_ASYNC16(saddr, gaddr) \
    asm volatile("cp.async.ca.shared.global [%0], [%1], 16;" \
                 :: "r"(saddr), "l"(gaddr) : "memory")
#define CP_COMMIT() asm volatile("cp.async.commit_group;" ::: "memory")
#define CP_WAIT(n)  asm volatile("cp.async.wait_group %0;" :: "n"(n) : "memory")

// ---------------------------------------------------------------------------
// weight split: fp32 -> (hi fp16, lo fp16);  x convert: fp32 -> hi fp16 only
// ---------------------------------------------------------------------------
__global__ void split_w(const float* __restrict__ in,
                        __half* __restrict__ hi,
                        __half* __restrict__ lo, int n4) {
    int i = blockIdx.x * blockDim.x + threadIdx.x;
    if (i >= n4) return;
    float4 v = ((const float4*)in)[i];
    uint32_t h0 = packh(v.x, v.y), h1 = packh(v.z, v.w);
    uint32_t l0 = packh(v.x - lowh(h0), v.y - hih(h0));
    uint32_t l1 = packh(v.z - lowh(h1), v.w - hih(h1));
    ((uint2*)hi)[i] = make_uint2(h0, h1);
    ((uint2*)lo)[i] = make_uint2(l0, l1);
}
__global__ void conv_x(const float* __restrict__ in,
                       __half* __restrict__ hi, int n4) {
    int i = blockIdx.x * blockDim.x + threadIdx.x;
    if (i >= n4) return;
    float4 v = ((const float4*)in)[i];
    ((uint2*)hi)[i] = make_uint2(packh(v.x, v.y), packh(v.z, v.w));
}

// ---------------------------------------------------------------------------
// fp16 2-term tensor-core GEMM: C[M,768] = A[M,768] * W[768,768]^T + bias
// A 1-limb, W 2-limb:  C = Ahi*Whi + Ahi*Wlo.
// CTA 128x128, K-block 32, 8 warps (2Mx4N).
// 3-stage cp.async ring, ONE __syncthreads per iteration.
// ---------------------------------------------------------------------------
#define GKD    768
#define GROWB  80
#define GOFF_AHI 0
#define GOFF_BHI 10240
#define GOFF_BLO 20480
#define GBUF   30720
#define GSMEM_TOTAL (3 * GBUF)
#define GKB    (GKD / 32)          // 24 K-blocks

__global__ __launch_bounds__(256)
void gemm_mma_2t(const __half* __restrict__ Ahi,
                 const __half* __restrict__ Bhi,
                 const __half* __restrict__ Blo,
                 const float* __restrict__ bias,
                 float* __restrict__ Cf,
                 __half* __restrict__ Chi,
                 __half* __restrict__ Clo) {
    extern __shared__ char smc[];
    const uint32_t sb = smem_u32(smc);
    const int tid  = threadIdx.x;
    const int lane = tid & 31;
    const int wid  = tid >> 5;
    const int wm   = wid & 1;
    const int wn   = wid >> 1;
    const int m0 = blockIdx.y * 128;
    const int n0 = blockIdx.x * 128;

    const char* gp[3] = {
        (const char*)(Ahi + (size_t)m0 * GKD),
        (const char*)(Bhi + (size_t)n0 * GKD),
        (const char*)(Blo + (size_t)n0 * GKD)};
    const uint32_t soff[3] = {GOFF_AHI, GOFF_BHI, GOFF_BLO};

    const int r0c = (tid * 2) >> 2, c0c = (tid * 2) & 3;
    const int r1c = (tid * 2 + 1) >> 2, c1c = (tid * 2 + 1) & 3;

#define GISSUE(kb, buf) do {                                                   \
    const uint32_t bb = sb + (buf) * GBUF;                                     \
    _Pragma("unroll")                                                          \
    for (int mat = 0; mat < 3; mat++) {                                        \
        CP_ASYNC16(bb + soff[mat] + r0c * GROWB + c0c * 16,                    \
                   gp[mat] + (size_t)r0c * (GKD * 2) + (kb) * 64 + c0c * 16);  \
        CP_ASYNC16(bb + soff[mat] + r1c * GROWB + c1c * 16,                    \
                   gp[mat] + (size_t)r1c * (GKD * 2) + (kb) * 64 + c1c * 16);  \
    }                                                                          \
    CP_COMMIT();                                                               \
} while (0)

    float acc[4][4][4];
#pragma unroll
    for (int mt = 0; mt < 4; mt++)
#pragma unroll
        for (int nt = 0; nt < 4; nt++)
#pragma unroll
            for (int k = 0; k < 4; k++) acc[mt][nt][k] = 0.f;

    const uint32_t a_row  = wm * 64 + (lane & 15);
    const uint32_t a_koff = (lane >> 4) << 4;
    // paired B ldsm_x4: lanes 0-15 first 8-row group, 16-31 second
    const uint32_t b_row  = wn * 32 + ((lane >> 4) << 3) + (lane & 7);
    const uint32_t b_koff = ((lane >> 3) & 1) << 4;

    GISSUE(0, 0);
    GISSUE(1, 1);

    for (int kb = 0; kb < GKB; kb++) {
        if (kb + 1 < GKB) { CP_WAIT(1); } else { CP_WAIT(0); }
        __syncthreads();

        const uint32_t bb = sb + (kb % 3) * GBUF;
#pragma unroll
        for (int kk = 0; kk < 2; kk++) {
            const uint32_t ka = kk * 32 + a_koff;
            const uint32_t kbf = kk * 32 + b_koff;
            uint32_t ahi[4][4], bhi[4][2], blo[4][2];
#pragma unroll
            for (int mt = 0; mt < 4; mt++)
                ldsm_x4(ahi[mt], bb + GOFF_AHI + (a_row + mt * 16) * GROWB + ka);
#pragma unroll
            for (int p = 0; p < 2; p++) {
                ldsm_x4(&bhi[2 * p][0],
                        bb + GOFF_BHI + (b_row + p * 16) * GROWB + kbf);
                ldsm_x4(&blo[2 * p][0],
                        bb + GOFF_BLO + (b_row + p * 16) * GROWB + kbf);
            }
#pragma unroll
            for (int mt = 0; mt < 4; mt++)
#pragma unroll
                for (int nt = 0; nt < 4; nt++) {
                    mma_f16(acc[mt][nt], ahi[mt], bhi[nt]);
                    mma_f16(acc[mt][nt], ahi[mt], blo[nt]);
                }
        }
        // loads for kb+2 go into the buffer consumed at kb-1; every warp has
        // passed this iteration's barrier, so that compute is complete.
        if (kb + 2 < GKB) GISSUE(kb + 2, (kb + 2) % 3);
    }

    // epilogue: +bias, write fp32 or fp16 2-limb
#pragma unroll
    for (int nt = 0; nt < 4; nt++) {
        const int n = n0 + wn * 32 + nt * 8 + (lane & 3) * 2;
        const float b0 = bias[n], b1 = bias[n + 1];
#pragma unroll
        for (int mt = 0; mt < 4; mt++) {
            const int m = m0 + wm * 64 + mt * 16 + (lane >> 2);
            const float v00 = acc[mt][nt][0] + b0, v01 = acc[mt][nt][1] + b1;
            const float v10 = acc[mt][nt][2] + b0, v11 = acc[mt][nt][3] + b1;
            if (Cf) {
                *(float2*)&Cf[(size_t)m * GKD + n] = make_float2(v00, v01);
                *(float2*)&Cf[(size_t)(m + 8) * GKD + n] = make_float2(v10, v11);
            } else {
                uint32_t h0 = packh(v00, v01);
                uint32_t l0 = packh(v00 - lowh(h0), v01 - hih(h0));
                uint32_t h1 = packh(v10, v11);
                uint32_t l1 = packh(v10 - lowh(h1), v11 - hih(h1));
                *(uint32_t*)&Chi[(size_t)m * GKD + n] = h0;
                *(uint32_t*)&Clo[(size_t)m * GKD + n] = l0;
                *(uint32_t*)&Chi[(size_t)(m + 8) * GKD + n] = h1;
                *(uint32_t*)&Clo[(size_t)(m + 8) * GKD + n] = l1;
            }
        }
    }
#undef GISSUE
}

// ---------------------------------------------------------------------------
// fp16 2-term flash attention.  Q 1-limb (=Khi), K-tile 2-limb, P 1-limb,
// V 2-limb:  S = Qhi*(Khi+Klo);  O = Phi*(Vhi+Vlo).
// K-tile = 64 keys, 2 CTAs/SM.  3-stage K ring, ONE __syncthreads per iter.
// ---------------------------------------------------------------------------
#define APITCH 144
#define ASQH   0
#define ASK    18432            // + buf*18432 ; lo at +9216
#define AKBUF  18432
#define ASMEM_TOTAL (18432 + 3 * AKBUF)
#define AKT    (L_ / 64)         // 16 K-tiles

__global__ __launch_bounds__(256, 2)
void attn_mma(const __half* __restrict__ Khi,
              const __half* __restrict__ Klo,
              const int* __restrict__ mask,
              __half* __restrict__ Vout) {
    extern __shared__ char smc[];
    const uint32_t sb = smem_u32(smc);
    const int tid  = threadIdx.x;
    const int lane = tid & 31;
    const int w    = tid >> 5;
    const int q0 = blockIdx.x * 128;
    const int h  = blockIdx.y;
    const int b  = blockIdx.z;

    const size_t gk = ((size_t)b * L_) * D_ + h * DH_;
    const size_t gq = gk + (size_t)q0 * D_;

    const int qrow[4] = {(tid + 0) >> 3, (tid + 256) >> 3,
                         (tid + 512) >> 3, (tid + 768) >> 3};
    const int qcol[4] = {(tid + 0) & 7, (tid + 256) & 7,
                         (tid + 512) & 7, (tid + 768) & 7};
    const int kr0 = tid >> 3,           kc0 = tid & 7;
    const int kr1 = (tid + 256) >> 3,   kc1 = (tid + 256) & 7;

#define AISSUE_K(kt, buf) do {                                                 \
    const uint32_t dh = sb + ASK + (buf) * AKBUF;                              \
    const __half* ghx = Khi + gk + (size_t)(kt) * 64 * D_;                     \
    const __half* glx = Klo + gk + (size_t)(kt) * 64 * D_;                     \
    const uint32_t s0 = kr0 * APITCH + kc0 * 16;                               \
    const uint32_t s1 = kr1 * APITCH + kc1 * 16;                               \
    const size_t g0 = (size_t)kr0 * D_ + kc0 * 8;                              \
    const size_t g1 = (size_t)kr1 * D_ + kc1 * 8;                              \
    CP_ASYNC16(dh + s0, (const char*)(ghx + g0));                              \
    CP_ASYNC16(dh + s1, (const char*)(ghx + g1));                              \
    CP_ASYNC16(dh + 9216 + s0, (const char*)(glx + g0));                       \
    CP_ASYNC16(dh + 9216 + s1, (const char*)(glx + g1));                       \
    CP_COMMIT();                                                               \
} while (0)

    {
#pragma unroll
        for (int i = 0; i < 4; i++) {
            const uint32_t so = qrow[i] * APITCH + qcol[i] * 16;
            const size_t go = (size_t)qrow[i] * D_ + qcol[i] * 8;
            CP_ASYNC16(sb + ASQH + so, (const char*)(Khi + gq + go));
        }
        CP_COMMIT();
    }
    AISSUE_K(0, 0);
    AISSUE_K(1, 1);

    CP_WAIT(2);                 // Q group complete; K0/K1 still in flight
    __syncthreads();

    uint32_t qh[4][4];
#pragma unroll
    for (int ks = 0; ks < 4; ks++) {
        const uint32_t a = sb + ASQH + (w * 16 + (lane & 15)) * APITCH +
                           ks * 32 + ((lane >> 4) << 4);
        ldsm_x4(qh[ks], a);
    }

    const bool rm0 = (__ldg(&mask[b * L_ + q0 + w * 16 + (lane >> 2)]) == 0);
    const bool rm1 = (__ldg(&mask[b * L_ + q0 + w * 16 + (lane >> 2) + 8]) == 0);
    const float kscale = 0.03608439182435161f * 1.4426950408889634f;

    float m0 = -3e38f, m1 = -3e38f, l0 = 0.f, l1 = 0.f;
    float o[8][4];
#pragma unroll
    for (int dn = 0; dn < 8; dn++)
#pragma unroll
        for (int j = 0; j < 4; j++) o[dn][j] = 0.f;

    for (int kt = 0; kt < AKT; kt++) {
        if (kt + 1 < AKT) { CP_WAIT(1); } else { CP_WAIT(0); }
        __syncthreads();
        const uint32_t kb = sb + ASK + (kt % 3) * AKBUF;

        // ---- S = Qhi * (Khi + Klo) ----
        float s[8][4];
#pragma unroll
        for (int nb = 0; nb < 8; nb++)
#pragma unroll
            for (int j = 0; j < 4; j++) s[nb][j] = 0.f;

#pragma unroll
        for (int nb = 0; nb < 8; nb++) {
            uint32_t bh[8], bl[8];
            const uint32_t a0 = kb + (nb * 8 + (lane & 7)) * APITCH +
                                ((lane >> 3) << 4);
            ldsm_x4(bh, a0);
            ldsm_x4(bh + 4, a0 + 64);
            ldsm_x4(bl, a0 + 9216);
            ldsm_x4(bl + 4, a0 + 9216 + 64);
#pragma unroll
            for (int ks = 0; ks < 4; ks++) {
                mma_f16(s[nb], qh[ks], bh + ks * 2);
                mma_f16(s[nb], qh[ks], bl + ks * 2);
            }
        }

        // ---- online softmax (exp2 domain) ----
        float tm0 = -3e38f, tm1 = -3e38f;
#pragma unroll
        for (int nb = 0; nb < 8; nb++) {
            s[nb][0] = rm0 ? -1e9f : s[nb][0] * kscale;
            s[nb][1] = rm0 ? -1e9f : s[nb][1] * kscale;
            s[nb][2] = rm1 ? -1e9f : s[nb][2] * kscale;
            s[nb][3] = rm1 ? -1e9f : s[nb][3] * kscale;
            tm0 = fmaxf(tm0, fmaxf(s[nb][0], s[nb][1]));
            tm1 = fmaxf(tm1, fmaxf(s[nb][2], s[nb][3]));
        }
        tm0 = fmaxf(tm0, __shfl_xor_sync(0xffffffffu, tm0, 1));
        tm0 = fmaxf(tm0, __shfl_xor_sync(0xffffffffu, tm0, 2));
        tm1 = fmaxf(tm1, __shfl_xor_sync(0xffffffffu, tm1, 1));
        tm1 = fmaxf(tm1, __shfl_xor_sync(0xffffffffu, tm1, 2));
        const float nm0 = fmaxf(m0, tm0), nm1 = fmaxf(m1, tm1);
        const float c0 = ex2f(m0 - nm0), c1 = ex2f(m1 - nm1);
        m0 = nm0; m1 = nm1;

        float ts0 = 0.f, ts1 = 0.f;
#pragma unroll
        for (int nb = 0; nb < 8; nb++) {
            s[nb][0] = ex2f(s[nb][0] - nm0);
            s[nb][1] = ex2f(s[nb][1] - nm0);
            s[nb][2] = ex2f(s[nb][2] - nm1);
            s[nb][3] = ex2f(s[nb][3] - nm1);
            ts0 += s[nb][0] + s[nb][1];
            ts1 += s[nb][2] + s[nb][3];
        }
        l0 = l0 * c0 + ts0;
        l1 = l1 * c1 + ts1;
#pragma unroll
        for (int dn = 0; dn < 8; dn++) {
            o[dn][0] *= c0; o[dn][1] *= c0;
            o[dn][2] *= c1; o[dn][3] *= c1;
        }

        // ---- O += Phi * (Vhi + Vlo), V = K tile ----
#pragma unroll
        for (int kk = 0; kk < 4; kk++) {
            uint32_t ph[4];
            {
                const float* sA = s[kk * 2];
                const float* sB = s[kk * 2 + 1];
                ph[0] = packh(sA[0], sA[1]);
                ph[1] = packh(sA[2], sA[3]);
                ph[2] = packh(sB[0], sB[1]);
                ph[3] = packh(sB[2], sB[3]);
            }
#pragma unroll
            for (int dn2 = 0; dn2 < 4; dn2++) {
                uint32_t vh[4], vl[4];
                const uint32_t a = kb + (kk * 16 + (lane & 15)) * APITCH +
                                   dn2 * 32 + ((lane >> 4) << 4);
                ldsm_x4t(vh, a);
                ldsm_x4t(vl, a + 9216);
                mma_f16(o[dn2 * 2],     ph, vh);
                mma_f16(o[dn2 * 2],     ph, vl);
                mma_f16(o[dn2 * 2 + 1], ph, vh + 2);
                mma_f16(o[dn2 * 2 + 1], ph, vl + 2);
            }
        }

        // loads for kt+2 target the buffer consumed at kt-1 (safe: all warps
        // passed this iteration's barrier).
        if (kt + 2 < AKT) AISSUE_K(kt + 2, (kt + 2) % 3);
    }

    // ---- epilogue: normalize, store 1-limb fp16 ----
    l0 += __shfl_xor_sync(0xffffffffu, l0, 1);
    l0 += __shfl_xor_sync(0xffffffffu, l0, 2);
    l1 += __shfl_xor_sync(0xffffffffu, l1, 1);
    l1 += __shfl_xor_sync(0xffffffffu, l1, 2);
    const float inv0 = 1.0f / l0, inv1 = 1.0f / l1;
    const int qa = q0 + w * 16 + (lane >> 2);
    const size_t ra = ((size_t)b * L_ + qa) * D_ + h * DH_;
    const size_t rb = ra + (size_t)8 * D_;
#pragma unroll
    for (int dn = 0; dn < 8; dn++) {
        const int col = dn * 8 + (lane & 3) * 2;
        *(uint32_t*)&Vout[ra + col] = packh(o[dn][0] * inv0, o[dn][1] * inv0);
        *(uint32_t*)&Vout[rb + col] = packh(o[dn][2] * inv1, o[dn][3] * inv1);
    }
#undef AISSUE_K
}

// ---------------------------------------------------------------------------
// Launch. Inputs: 0:x 1:mask 2:Wq 3:bq 4:Wk 5:bk 6:Wv 7:bv 8:Wo 9:bo
// (Q projection and Wv/bv are dead in the reference: V = K, scores = K K^T.)
// ---------------------------------------------------------------------------
extern "C" void kernel_launch(void* const* d_in, const int* in_sizes, int n_in,
                              void* d_out, int out_size) {
    const float* x    = (const float*)d_in[0];
    const int*   mask = (const int*)  d_in[1];
    const float* Wk   = (const float*)d_in[4];
    const float* bk   = (const float*)d_in[5];
    const float* Wo   = (const float*)d_in[8];
    const float* bo   = (const float*)d_in[9];
    float* out = (float*)d_out;

    __half *pxhi, *pkhi, *pklo, *pvhi, *pwkhi, *pwklo, *pwohi, *pwolo;
    cudaGetSymbolAddress((void**)&pxhi,  g_xhi);
    cudaGetSymbolAddress((void**)&pkhi,  g_khi);
    cudaGetSymbolAddress((void**)&pklo,  g_klo);
    cudaGetSymbolAddress((void**)&pvhi,  g_vhi);
    cudaGetSymbolAddress((void**)&pwkhi, g_wkhi);
    cudaGetSymbolAddress((void**)&pwklo, g_wklo);
    cudaGetSymbolAddress((void**)&pwohi, g_wohi);
    cudaGetSymbolAddress((void**)&pwolo, g_wolo);

    cudaFuncSetAttribute(gemm_mma_2t,
                         cudaFuncAttributeMaxDynamicSharedMemorySize,
                         GSMEM_TOTAL);
    cudaFuncSetAttribute(attn_mma,
                         cudaFuncAttributeMaxDynamicSharedMemorySize,
                         ASMEM_TOTAL);

    const int M = B_ * L_;                    // 8192
    const int nx4 = M * D_ / 4;
    const int nw4 = D_ * D_ / 4;

    conv_x <<<(nx4 + 255) / 256, 256>>>(x,  pxhi,  nx4);
    split_w<<<(nw4 + 255) / 256, 256>>>(Wk, pwkhi, pwklo, nw4);
    split_w<<<(nw4 + 255) / 256, 256>>>(Wo, pwohi, pwolo, nw4);

    // 1) K = x @ Wk^T + bk  -> fp16 2-limb
    {
        dim3 grid(D_ / 128, M / 128);
        gemm_mma_2t<<<grid, 256, GSMEM_TOTAL>>>(pxhi, pwkhi, pwklo,
                                                bk, nullptr, pkhi, pklo);
    }
    // 2) fused flash attention -> fp16 1-limb
    {
        dim3 grid(L_ / 128, H_, B_);
        attn_mma<<<grid, 256, ASMEM_TOTAL>>>(pkhi, pklo, mask, pvhi);
    }
    // 3) out = wV @ Wo^T + bo  -> fp32
    {
        dim3 grid(D_ / 128, M / 128);
        gemm_mma_2t<<<grid, 256, GSMEM_TOTAL>>>(pvhi, pwohi, pwolo,
                                                bo, out, nullptr, nullptr);
    }
}